// round 7
// baseline (speedup 1.0000x reference)
#include <cuda_runtime.h>
#include <math.h>

#define NGRAPH 128
#define FDIM   64
#define MAXN   100000
#define MAXE   1600000
#define GEPS   1e-5f

// ---------------- device scratch ----------------
__device__ float g_dinv[MAXN];
__device__ float g_cnt[NGRAPH];
__device__ float g_cinv[NGRAPH];
__device__ float g_bufA[MAXN * FDIM];
__device__ float g_bufB[MAXN * FDIM];
__device__ float g_gsum[NGRAPH * FDIM];
__device__ float g_gsq[NGRAPH * FDIM];
__device__ float g_scale[NGRAPH * FDIM];
__device__ float g_shift[NGRAPH * FDIM];
__device__ int   g_indeg[MAXN];
__device__ int   g_off[MAXN];
__device__ int   g_cursor[MAXN];
__device__ int   g_csr[MAXE];
__device__ int   g_bsum[512];

// ---------------- host-side aux (created once, before any capture) -------
namespace {
struct Aux {
    cudaStream_t s2;
    cudaEvent_t  evFork, evJoin;
    Aux() {
        cudaStreamCreateWithFlags(&s2, cudaStreamNonBlocking);
        cudaEventCreateWithFlags(&evFork, cudaEventDisableTiming);
        cudaEventCreateWithFlags(&evJoin, cudaEventDisableTiming);
    }
};
Aux g_aux;  // constructed at static-init time, outside graph capture
}

// ---------------- helpers ----------------
__device__ __forceinline__ void red_add_v2(float* p, float2 v) {
    asm volatile("red.global.add.v2.f32 [%0], {%1,%2};"
                 :: "l"(p), "f"(v.x), "f"(v.y) : "memory");
}
__device__ __forceinline__ void red_add_v4(float* p, float4 v) {
    asm volatile("red.global.add.v4.f32 [%0], {%1,%2,%3,%4};"
                 :: "l"(p), "f"(v.x), "f"(v.y), "f"(v.z), "f"(v.w) : "memory");
}

// ---------------- init ----------------
__global__ void k_init(float* out, int N) {
    int i = blockIdx.x * blockDim.x + threadIdx.x;
    if (i < N) g_indeg[i] = 0;
    if (i < NGRAPH) g_cnt[i] = 0.0f;
    if (i < NGRAPH * FDIM) {
        g_gsum[i] = 0.0f;
        g_gsq[i]  = 0.0f;
        out[i]    = 0.0f;
    }
}

__global__ void k_deg(const int* __restrict__ dst, int E) {
    int i = blockIdx.x * blockDim.x + threadIdx.x;
    if (i < E) atomicAdd(&g_indeg[dst[i]], 1);
}

// ---------------- scan: block totals ----------------
__global__ void k_scan1(int N) {
    int t = threadIdx.x;
    int i = blockIdx.x * 256 + t;
    int v = (i < N) ? g_indeg[i] : 0;
    __shared__ int s[256];
    s[t] = v; __syncthreads();
    for (int d = 128; d > 0; d >>= 1) {
        if (t < d) s[t] += s[t + d];
        __syncthreads();
    }
    if (t == 0) g_bsum[blockIdx.x] = s[0];
}

// ---------------- scan: block offset (inline) + intra-block scan ---------
__global__ void k_scan3(const int* __restrict__ batch, int N, int nb) {
    int t = threadIdx.x;
    int b = blockIdx.x;
    int i = b * 256 + t;
    __shared__ int s[256];
    __shared__ int blockOff;

    // phase 1: sum of g_bsum[0..b-1]
    int acc = 0;
    if (t < b)        acc += g_bsum[t];
    if (t + 256 < b)  acc += g_bsum[t + 256];
    s[t] = acc; __syncthreads();
    for (int d = 128; d > 0; d >>= 1) {
        if (t < d) s[t] += s[t + d];
        __syncthreads();
    }
    if (t == 0) blockOff = s[0];
    __syncthreads();

    // phase 2: intra-block inclusive scan
    int v = (i < N) ? g_indeg[i] : 0;
    s[t] = v; __syncthreads();
    for (int d = 1; d < 256; d <<= 1) {
        int x = (t >= d) ? s[t - d] : 0;
        __syncthreads();
        s[t] += x;
        __syncthreads();
    }
    int excl = s[t] - v + blockOff;
    if (i < N) {
        g_off[i]    = excl;
        g_cursor[i] = excl;
        g_dinv[i]   = rsqrtf((float)(v + 1));   // +1 self loop
        atomicAdd(&g_cnt[batch[i]], 1.0f);
    }
}

__global__ void k_fill(const int* __restrict__ src, const int* __restrict__ dst, int E) {
    int i = blockIdx.x * blockDim.x + threadIdx.x;
    if (i < E) {
        int pos = atomicAdd(&g_cursor[dst[i]], 1);
        g_csr[pos] = src[i];
    }
}

// ---------------- GEMM: out[r,:] = f(X[r,:]) @ W  (NO dinv; applied in gather)
// FUSE: f = relu(x*scale+shift) per (batch[r], feature)
template<int K, bool FUSE>
__global__ __launch_bounds__(256)
void k_gemm(const float* __restrict__ X, const float* __restrict__ W,
            float* __restrict__ out, const int* __restrict__ batch, int N) {
    __shared__ float Ws[K][FDIM];
    __shared__ float Xs[64][17];
    __shared__ int   bs[64];

    int tid = threadIdx.x;
    int rowBase = blockIdx.x * 64;
    for (int i = tid; i < K * FDIM; i += 256)
        Ws[i / FDIM][i % FDIM] = W[i];
    if (FUSE && tid < 64) {
        int r = rowBase + tid;
        bs[tid] = (r < N) ? batch[r] : 0;
    }

    int ty = tid / 16;
    int tx = tid % 16;
    float acc[4][4] = {};

    for (int kc = 0; kc < K; kc += 16) {
        __syncthreads();
        for (int i = tid; i < 64 * 16; i += 256) {
            int m = i / 16, k = i % 16;
            int r = rowBase + m;
            float val = 0.0f;
            if (r < N) {
                int f = kc + k;
                val = X[(size_t)r * K + f];
                if (FUSE) {
                    int g = bs[m];
                    val = fmaxf(fmaf(val, g_scale[g * FDIM + f], g_shift[g * FDIM + f]), 0.0f);
                }
            }
            Xs[m][k] = val;
        }
        __syncthreads();
        #pragma unroll
        for (int k = 0; k < 16; ++k) {
            const float4 wf = *(const float4*)(&Ws[kc + k][tx * 4]);
            float xv[4];
            #pragma unroll
            for (int i = 0; i < 4; ++i) xv[i] = Xs[ty * 4 + i][k];
            #pragma unroll
            for (int i = 0; i < 4; ++i) {
                acc[i][0] = fmaf(xv[i], wf.x, acc[i][0]);
                acc[i][1] = fmaf(xv[i], wf.y, acc[i][1]);
                acc[i][2] = fmaf(xv[i], wf.z, acc[i][2]);
                acc[i][3] = fmaf(xv[i], wf.w, acc[i][3]);
            }
        }
    }

    #pragma unroll
    for (int i = 0; i < 4; ++i) {
        int r = rowBase + ty * 4 + i;
        if (r < N) {
            float4 v = make_float4(acc[i][0], acc[i][1], acc[i][2], acc[i][3]);
            *(float4*)&out[(size_t)r * FDIM + tx * 4] = v;
        }
    }
}

// ---------------- gather + conv epilogue + graph stats -------------------
// B[d] = (Σ_{s∈nbr(d)} A[s]*dinv[s] + A[d]*dinv[d]) * dinv[d] + b
__global__ __launch_bounds__(256)
void k_gather(const float* __restrict__ A, float* __restrict__ B,
              const float* __restrict__ bvec, const int* __restrict__ batch, int N) {
    int warp = (blockIdx.x * blockDim.x + threadIdx.x) >> 5;
    int lane = threadIdx.x & 31;
    if (warp >= N) return;

    int start = g_off[warp];
    int deg   = g_indeg[warp];
    int end   = start + deg;
    size_t fo = (size_t)lane * 2;

    float dinv = g_dinv[warp];
    float2 b   = *(const float2*)(bvec + fo);
    int    g   = batch[warp];

    float2 sv = *(const float2*)(A + (size_t)warp * FDIM + fo);  // self
    float2 a0 = make_float2(sv.x * dinv, sv.y * dinv);
    float2 a1 = make_float2(0.f, 0.f);
    float2 a2 = make_float2(0.f, 0.f);
    float2 a3 = make_float2(0.f, 0.f);

    int j = start;
    for (; j + 8 <= end; j += 8) {
        int s0 = __ldg(&g_csr[j]);
        int s1 = __ldg(&g_csr[j + 1]);
        int s2 = __ldg(&g_csr[j + 2]);
        int s3 = __ldg(&g_csr[j + 3]);
        int s4 = __ldg(&g_csr[j + 4]);
        int s5 = __ldg(&g_csr[j + 5]);
        int s6 = __ldg(&g_csr[j + 6]);
        int s7 = __ldg(&g_csr[j + 7]);
        float d0 = __ldg(&g_dinv[s0]);
        float d1 = __ldg(&g_dinv[s1]);
        float d2 = __ldg(&g_dinv[s2]);
        float d3 = __ldg(&g_dinv[s3]);
        float d4 = __ldg(&g_dinv[s4]);
        float d5 = __ldg(&g_dinv[s5]);
        float d6 = __ldg(&g_dinv[s6]);
        float d7 = __ldg(&g_dinv[s7]);
        float2 v0 = *(const float2*)(A + (size_t)s0 * FDIM + fo);
        float2 v1 = *(const float2*)(A + (size_t)s1 * FDIM + fo);
        float2 v2 = *(const float2*)(A + (size_t)s2 * FDIM + fo);
        float2 v3 = *(const float2*)(A + (size_t)s3 * FDIM + fo);
        float2 v4 = *(const float2*)(A + (size_t)s4 * FDIM + fo);
        float2 v5 = *(const float2*)(A + (size_t)s5 * FDIM + fo);
        float2 v6 = *(const float2*)(A + (size_t)s6 * FDIM + fo);
        float2 v7 = *(const float2*)(A + (size_t)s7 * FDIM + fo);
        a0.x = fmaf(v0.x, d0, a0.x); a0.y = fmaf(v0.y, d0, a0.y);
        a1.x = fmaf(v1.x, d1, a1.x); a1.y = fmaf(v1.y, d1, a1.y);
        a2.x = fmaf(v2.x, d2, a2.x); a2.y = fmaf(v2.y, d2, a2.y);
        a3.x = fmaf(v3.x, d3, a3.x); a3.y = fmaf(v3.y, d3, a3.y);
        a0.x = fmaf(v4.x, d4, a0.x); a0.y = fmaf(v4.y, d4, a0.y);
        a1.x = fmaf(v5.x, d5, a1.x); a1.y = fmaf(v5.y, d5, a1.y);
        a2.x = fmaf(v6.x, d6, a2.x); a2.y = fmaf(v6.y, d6, a2.y);
        a3.x = fmaf(v7.x, d7, a3.x); a3.y = fmaf(v7.y, d7, a3.y);
    }
    for (; j < end; ++j) {
        int s0 = __ldg(&g_csr[j]);
        float d0 = __ldg(&g_dinv[s0]);
        float2 v0 = *(const float2*)(A + (size_t)s0 * FDIM + fo);
        a0.x = fmaf(v0.x, d0, a0.x); a0.y = fmaf(v0.y, d0, a0.y);
    }

    float2 v;
    v.x = fmaf(a0.x + a1.x + a2.x + a3.x, dinv, b.x);
    v.y = fmaf(a0.y + a1.y + a2.y + a3.y, dinv, b.y);
    *(float2*)(B + (size_t)warp * FDIM + fo) = v;

    red_add_v2(&g_gsum[g * FDIM + (int)fo], v);
    red_add_v2(&g_gsq [g * FDIM + (int)fo], make_float2(v.x * v.x, v.y * v.y));
}

// ---------------- per-(graph,feature) scale/shift; resets stats ----------
__global__ void k_stats(const float* __restrict__ alpha, const float* __restrict__ weight,
                        const float* __restrict__ bias) {
    int t = blockIdx.x * blockDim.x + threadIdx.x;
    if (t >= NGRAPH * FDIM) return;
    int g = t / FDIM, f = t % FDIM;
    float c = fmaxf(g_cnt[g], 1.0f);
    float mean = g_gsum[t] / c;
    float ex2  = g_gsq[t] / c;
    float a = alpha[f];
    float var = ex2 - (2.0f * a - a * a) * mean * mean;
    float istd = rsqrtf(var + GEPS);
    float sc = weight[f] * istd;
    g_scale[t] = sc;
    g_shift[t] = bias[f] - a * mean * sc;
    g_gsum[t] = 0.0f;
    g_gsq[t]  = 0.0f;
    if (t < NGRAPH) g_cinv[t] = 1.0f / fmaxf(g_cnt[t], 1.0f);
}

// ---------------- norm + relu + mean-pool (1/cnt folded in) --------------
__global__ void k_apply_pool(const float* __restrict__ in, float* __restrict__ dout,
                             const int* __restrict__ batch, int N) {
    int t = blockIdx.x * blockDim.x + threadIdx.x;
    if (t >= N * 16) return;
    int i = t >> 4;
    int c = t & 15;
    int g = batch[i];
    float ci = g_cinv[g];
    float4 sc = *(const float4*)&g_scale[g * FDIM + c * 4];
    float4 sh = *(const float4*)&g_shift[g * FDIM + c * 4];
    float4 v = *((const float4*)in + t);
    float4 r = make_float4(fmaxf(fmaf(v.x, sc.x, sh.x), 0.0f) * ci,
                           fmaxf(fmaf(v.y, sc.y, sh.y), 0.0f) * ci,
                           fmaxf(fmaf(v.z, sc.z, sh.z), 0.0f) * ci,
                           fmaxf(fmaf(v.w, sc.w, sh.w), 0.0f) * ci);
    red_add_v4(dout + g * FDIM + c * 4, r);
}

// ---------------- launcher ----------------
extern "C" void kernel_launch(void* const* d_in, const int* in_sizes, int n_in,
                              void* d_out, int out_size) {
    const float* x      = (const float*)d_in[0];
    const int*   ei     = (const int*)  d_in[1];
    const int*   batch  = (const int*)  d_in[2];
    const float* W1     = (const float*)d_in[3];
    const float* b1     = (const float*)d_in[4];
    const float* alpha1 = (const float*)d_in[5];
    const float* weight1= (const float*)d_in[6];
    const float* bias1  = (const float*)d_in[7];
    const float* W2     = (const float*)d_in[8];
    const float* b2     = (const float*)d_in[9];
    const float* alpha2 = (const float*)d_in[10];
    const float* weight2= (const float*)d_in[11];
    const float* bias2  = (const float*)d_in[12];
    float* out = (float*)d_out;

    int N = in_sizes[2];
    int E = in_sizes[1] / 2;
    const int* src = ei;
    const int* dst = ei + E;

    float *pA, *pB;
    cudaGetSymbolAddress((void**)&pA, g_bufA);
    cudaGetSymbolAddress((void**)&pB, g_bufB);

    const int T = 256;
    int nbN    = (N + T - 1) / T;
    int nbE    = (E + T - 1) / T;
    int nb16   = (N * 16 + T - 1) / T;
    int nbGF   = (NGRAPH * FDIM + T - 1) / T;
    int nbRow  = (N + 63) / 64;
    int nbWarp = (N * 32 + T - 1) / T;

    // ---- fork: preprocess chain on side stream, GEMM1 concurrently ----
    cudaEventRecord(g_aux.evFork, 0);
    cudaStreamWaitEvent(g_aux.s2, g_aux.evFork, 0);

    k_init <<<nbN, T, 0, g_aux.s2>>>(out, N);
    k_deg  <<<nbE, T, 0, g_aux.s2>>>(dst, E);
    k_scan1<<<nbN, T, 0, g_aux.s2>>>(N);
    k_scan3<<<nbN, T, 0, g_aux.s2>>>(batch, N, nbN);
    k_fill <<<nbE, T, 0, g_aux.s2>>>(src, dst, E);
    cudaEventRecord(g_aux.evJoin, g_aux.s2);

    // GEMM1 is independent of preprocessing (no dinv applied here)
    k_gemm<128, false><<<nbRow, T>>>(x, W1, pA, batch, N);

    cudaStreamWaitEvent(0, g_aux.evJoin, 0);   // join before gather

    // ---- layer 1 ----
    k_gather<<<nbWarp, T>>>(pA, pB, b1, batch, N);
    k_stats <<<nbGF, T>>>(alpha1, weight1, bias1);

    // ---- layer 2 (norm+relu fused into gemm load) ----
    k_gemm<64, true><<<nbRow, T>>>(pB, W2, pA, batch, N);
    k_gather<<<nbWarp, T>>>(pA, pB, b2, batch, N);
    k_stats <<<nbGF, T>>>(alpha2, weight2, bias2);

    // ---- pool ----
    k_apply_pool<<<nb16, T>>>(pB, out, batch, N);
}

// round 9
// speedup vs baseline: 1.0224x; 1.0224x over previous
#include <cuda_runtime.h>
#include <math.h>

#define NGRAPH 128
#define FDIM   64
#define MAXN   100000
#define MAXE   1600000
#define GEPS   1e-5f

// ---------------- device scratch ----------------
__device__ float g_dinv[MAXN];
__device__ float g_cnt[NGRAPH];
__device__ float g_cinv[NGRAPH];
__device__ float g_bufA[MAXN * FDIM];
__device__ float g_bufB[MAXN * FDIM];
__device__ float g_gsum[NGRAPH * FDIM];
__device__ float g_gsq[NGRAPH * FDIM];
__device__ float g_scale[NGRAPH * FDIM];
__device__ float g_shift[NGRAPH * FDIM];
__device__ int   g_indeg[MAXN];
__device__ int   g_off[MAXN];
__device__ int   g_cursor[MAXN];
__device__ int   g_csr[MAXE];
__device__ int   g_total;

// ---------------- host-side aux (created once, before any capture) -------
namespace {
struct Aux {
    cudaStream_t s2;
    cudaEvent_t  evFork, evJoin;
    Aux() {
        cudaStreamCreateWithFlags(&s2, cudaStreamNonBlocking);
        cudaEventCreateWithFlags(&evFork, cudaEventDisableTiming);
        cudaEventCreateWithFlags(&evJoin, cudaEventDisableTiming);
    }
};
Aux g_aux;  // constructed at static-init time, outside graph capture
}

// ---------------- helpers ----------------
__device__ __forceinline__ void red_add_v2(float* p, float2 v) {
    asm volatile("red.global.add.v2.f32 [%0], {%1,%2};"
                 :: "l"(p), "f"(v.x), "f"(v.y) : "memory");
}
__device__ __forceinline__ void red_add_v4(float* p, float4 v) {
    asm volatile("red.global.add.v4.f32 [%0], {%1,%2,%3,%4};"
                 :: "l"(p), "f"(v.x), "f"(v.y), "f"(v.z), "f"(v.w) : "memory");
}

// ---------------- init ----------------
__global__ void k_init(float* out, int N) {
    int i = blockIdx.x * blockDim.x + threadIdx.x;
    if (i < N) g_indeg[i] = 0;
    if (i == 0) g_total = 0;
    if (i < NGRAPH) g_cnt[i] = 0.0f;
    if (i < NGRAPH * FDIM) {
        g_gsum[i] = 0.0f;
        g_gsq[i]  = 0.0f;
        out[i]    = 0.0f;
    }
}

__global__ void k_deg(const int* __restrict__ dst, int E) {
    int i = blockIdx.x * blockDim.x + threadIdx.x;
    if (i < E) atomicAdd(&g_indeg[dst[i]], 1);
}

// ---------------- CSR segment allocation: NO scan, NO barriers -----------
// Warp-aggregated atomic allocation. Segment order is irrelevant for the
// gather-sum, so a global atomic cursor replaces the exclusive prefix scan.
__global__ void k_alloc(const int* __restrict__ batch, int N) {
    int i = blockIdx.x * blockDim.x + threadIdx.x;
    int lane = threadIdx.x & 31;
    int v = (i < N) ? g_indeg[i] : 0;

    int incl = v;
    #pragma unroll
    for (int d = 1; d < 32; d <<= 1) {
        int x = __shfl_up_sync(0xFFFFFFFFu, incl, d);
        if (lane >= d) incl += x;
    }
    int base = 0;
    if (lane == 31) base = atomicAdd(&g_total, incl);
    base = __shfl_sync(0xFFFFFFFFu, base, 31);
    int excl = base + incl - v;

    if (i < N) {
        g_off[i]    = excl;
        g_cursor[i] = excl;
        g_dinv[i]   = rsqrtf((float)(v + 1));   // +1 self loop
        atomicAdd(&g_cnt[batch[i]], 1.0f);
    }
}

__global__ void k_fill(const int* __restrict__ src, const int* __restrict__ dst, int E) {
    int i = blockIdx.x * blockDim.x + threadIdx.x;
    if (i < E) {
        int pos = atomicAdd(&g_cursor[dst[i]], 1);
        g_csr[pos] = src[i];
    }
}

// ---------------- GEMM: out[r,:] = f(X[r,:]) @ W  (NO dinv; applied in gather)
// FUSE: f = relu(x*scale+shift) per (batch[r], feature)
template<int K, bool FUSE>
__global__ __launch_bounds__(256)
void k_gemm(const float* __restrict__ X, const float* __restrict__ W,
            float* __restrict__ out, const int* __restrict__ batch, int N) {
    __shared__ float Ws[K][FDIM];
    __shared__ float Xs[64][17];
    __shared__ int   bs[64];

    int tid = threadIdx.x;
    int rowBase = blockIdx.x * 64;
    for (int i = tid; i < K * FDIM; i += 256)
        Ws[i / FDIM][i % FDIM] = W[i];
    if (FUSE && tid < 64) {
        int r = rowBase + tid;
        bs[tid] = (r < N) ? batch[r] : 0;
    }

    int ty = tid / 16;
    int tx = tid % 16;
    float acc[4][4] = {};

    for (int kc = 0; kc < K; kc += 16) {
        __syncthreads();
        for (int i = tid; i < 64 * 16; i += 256) {
            int m = i / 16, k = i % 16;
            int r = rowBase + m;
            float val = 0.0f;
            if (r < N) {
                int f = kc + k;
                val = X[(size_t)r * K + f];
                if (FUSE) {
                    int g = bs[m];
                    val = fmaxf(fmaf(val, g_scale[g * FDIM + f], g_shift[g * FDIM + f]), 0.0f);
                }
            }
            Xs[m][k] = val;
        }
        __syncthreads();
        #pragma unroll
        for (int k = 0; k < 16; ++k) {
            const float4 wf = *(const float4*)(&Ws[kc + k][tx * 4]);
            float xv[4];
            #pragma unroll
            for (int i = 0; i < 4; ++i) xv[i] = Xs[ty * 4 + i][k];
            #pragma unroll
            for (int i = 0; i < 4; ++i) {
                acc[i][0] = fmaf(xv[i], wf.x, acc[i][0]);
                acc[i][1] = fmaf(xv[i], wf.y, acc[i][1]);
                acc[i][2] = fmaf(xv[i], wf.z, acc[i][2]);
                acc[i][3] = fmaf(xv[i], wf.w, acc[i][3]);
            }
        }
    }

    #pragma unroll
    for (int i = 0; i < 4; ++i) {
        int r = rowBase + ty * 4 + i;
        if (r < N) {
            float4 v = make_float4(acc[i][0], acc[i][1], acc[i][2], acc[i][3]);
            *(float4*)&out[(size_t)r * FDIM + tx * 4] = v;
        }
    }
}

// ---------------- gather + conv epilogue + graph stats -------------------
// B[d] = (Σ_{s∈nbr(d)} A[s]*dinv[s] + A[d]*dinv[d]) * dinv[d] + b
__global__ __launch_bounds__(256)
void k_gather(const float* __restrict__ A, float* __restrict__ B,
              const float* __restrict__ bvec, const int* __restrict__ batch, int N) {
    int warp = (blockIdx.x * blockDim.x + threadIdx.x) >> 5;
    int lane = threadIdx.x & 31;
    if (warp >= N) return;

    int start = g_off[warp];
    int deg   = g_indeg[warp];
    int end   = start + deg;
    size_t fo = (size_t)lane * 2;

    float dinv = g_dinv[warp];
    float2 b   = *(const float2*)(bvec + fo);
    int    g   = batch[warp];

    float2 sv = *(const float2*)(A + (size_t)warp * FDIM + fo);  // self
    float2 a0 = make_float2(sv.x * dinv, sv.y * dinv);
    float2 a1 = make_float2(0.f, 0.f);
    float2 a2 = make_float2(0.f, 0.f);
    float2 a3 = make_float2(0.f, 0.f);

    int j = start;
    for (; j + 8 <= end; j += 8) {
        int s0 = __ldg(&g_csr[j]);
        int s1 = __ldg(&g_csr[j + 1]);
        int s2 = __ldg(&g_csr[j + 2]);
        int s3 = __ldg(&g_csr[j + 3]);
        int s4 = __ldg(&g_csr[j + 4]);
        int s5 = __ldg(&g_csr[j + 5]);
        int s6 = __ldg(&g_csr[j + 6]);
        int s7 = __ldg(&g_csr[j + 7]);
        float d0 = __ldg(&g_dinv[s0]);
        float d1 = __ldg(&g_dinv[s1]);
        float d2 = __ldg(&g_dinv[s2]);
        float d3 = __ldg(&g_dinv[s3]);
        float d4 = __ldg(&g_dinv[s4]);
        float d5 = __ldg(&g_dinv[s5]);
        float d6 = __ldg(&g_dinv[s6]);
        float d7 = __ldg(&g_dinv[s7]);
        float2 v0 = *(const float2*)(A + (size_t)s0 * FDIM + fo);
        float2 v1 = *(const float2*)(A + (size_t)s1 * FDIM + fo);
        float2 v2 = *(const float2*)(A + (size_t)s2 * FDIM + fo);
        float2 v3 = *(const float2*)(A + (size_t)s3 * FDIM + fo);
        float2 v4 = *(const float2*)(A + (size_t)s4 * FDIM + fo);
        float2 v5 = *(const float2*)(A + (size_t)s5 * FDIM + fo);
        float2 v6 = *(const float2*)(A + (size_t)s6 * FDIM + fo);
        float2 v7 = *(const float2*)(A + (size_t)s7 * FDIM + fo);
        a0.x = fmaf(v0.x, d0, a0.x); a0.y = fmaf(v0.y, d0, a0.y);
        a1.x = fmaf(v1.x, d1, a1.x); a1.y = fmaf(v1.y, d1, a1.y);
        a2.x = fmaf(v2.x, d2, a2.x); a2.y = fmaf(v2.y, d2, a2.y);
        a3.x = fmaf(v3.x, d3, a3.x); a3.y = fmaf(v3.y, d3, a3.y);
        a0.x = fmaf(v4.x, d4, a0.x); a0.y = fmaf(v4.y, d4, a0.y);
        a1.x = fmaf(v5.x, d5, a1.x); a1.y = fmaf(v5.y, d5, a1.y);
        a2.x = fmaf(v6.x, d6, a2.x); a2.y = fmaf(v6.y, d6, a2.y);
        a3.x = fmaf(v7.x, d7, a3.x); a3.y = fmaf(v7.y, d7, a3.y);
    }
    // 4-wide remainder step: keeps loads batched for deg%8 in [4,7]
    if (j + 4 <= end) {
        int s0 = __ldg(&g_csr[j]);
        int s1 = __ldg(&g_csr[j + 1]);
        int s2 = __ldg(&g_csr[j + 2]);
        int s3 = __ldg(&g_csr[j + 3]);
        float d0 = __ldg(&g_dinv[s0]);
        float d1 = __ldg(&g_dinv[s1]);
        float d2 = __ldg(&g_dinv[s2]);
        float d3 = __ldg(&g_dinv[s3]);
        float2 v0 = *(const float2*)(A + (size_t)s0 * FDIM + fo);
        float2 v1 = *(const float2*)(A + (size_t)s1 * FDIM + fo);
        float2 v2 = *(const float2*)(A + (size_t)s2 * FDIM + fo);
        float2 v3 = *(const float2*)(A + (size_t)s3 * FDIM + fo);
        a0.x = fmaf(v0.x, d0, a0.x); a0.y = fmaf(v0.y, d0, a0.y);
        a1.x = fmaf(v1.x, d1, a1.x); a1.y = fmaf(v1.y, d1, a1.y);
        a2.x = fmaf(v2.x, d2, a2.x); a2.y = fmaf(v2.y, d2, a2.y);
        a3.x = fmaf(v3.x, d3, a3.x); a3.y = fmaf(v3.y, d3, a3.y);
        j += 4;
    }
    for (; j < end; ++j) {
        int s0 = __ldg(&g_csr[j]);
        float d0 = __ldg(&g_dinv[s0]);
        float2 v0 = *(const float2*)(A + (size_t)s0 * FDIM + fo);
        a0.x = fmaf(v0.x, d0, a0.x); a0.y = fmaf(v0.y, d0, a0.y);
    }

    float2 v;
    v.x = fmaf(a0.x + a1.x + a2.x + a3.x, dinv, b.x);
    v.y = fmaf(a0.y + a1.y + a2.y + a3.y, dinv, b.y);
    *(float2*)(B + (size_t)warp * FDIM + fo) = v;

    red_add_v2(&g_gsum[g * FDIM + (int)fo], v);
    red_add_v2(&g_gsq [g * FDIM + (int)fo], make_float2(v.x * v.x, v.y * v.y));
}

// ---------------- per-(graph,feature) scale/shift; resets stats ----------
__global__ void k_stats(const float* __restrict__ alpha, const float* __restrict__ weight,
                        const float* __restrict__ bias) {
    int t = blockIdx.x * blockDim.x + threadIdx.x;
    if (t >= NGRAPH * FDIM) return;
    int g = t / FDIM, f = t % FDIM;
    float c = fmaxf(g_cnt[g], 1.0f);
    float mean = g_gsum[t] / c;
    float ex2  = g_gsq[t] / c;
    float a = alpha[f];
    float var = ex2 - (2.0f * a - a * a) * mean * mean;
    float istd = rsqrtf(var + GEPS);
    float sc = weight[f] * istd;
    g_scale[t] = sc;
    g_shift[t] = bias[f] - a * mean * sc;
    g_gsum[t] = 0.0f;
    g_gsq[t]  = 0.0f;
    if (t < NGRAPH) g_cinv[t] = 1.0f / fmaxf(g_cnt[t], 1.0f);
}

// ---------------- norm + relu + mean-pool (1/cnt folded in) --------------
__global__ void k_apply_pool(const float* __restrict__ in, float* __restrict__ dout,
                             const int* __restrict__ batch, int N) {
    int t = blockIdx.x * blockDim.x + threadIdx.x;
    if (t >= N * 16) return;
    int i = t >> 4;
    int c = t & 15;
    int g = batch[i];
    float ci = g_cinv[g];
    float4 sc = *(const float4*)&g_scale[g * FDIM + c * 4];
    float4 sh = *(const float4*)&g_shift[g * FDIM + c * 4];
    float4 v = *((const float4*)in + t);
    float4 r = make_float4(fmaxf(fmaf(v.x, sc.x, sh.x), 0.0f) * ci,
                           fmaxf(fmaf(v.y, sc.y, sh.y), 0.0f) * ci,
                           fmaxf(fmaf(v.z, sc.z, sh.z), 0.0f) * ci,
                           fmaxf(fmaf(v.w, sc.w, sh.w), 0.0f) * ci);
    red_add_v4(dout + g * FDIM + c * 4, r);
}

// ---------------- launcher ----------------
extern "C" void kernel_launch(void* const* d_in, const int* in_sizes, int n_in,
                              void* d_out, int out_size) {
    const float* x      = (const float*)d_in[0];
    const int*   ei     = (const int*)  d_in[1];
    const int*   batch  = (const int*)  d_in[2];
    const float* W1     = (const float*)d_in[3];
    const float* b1     = (const float*)d_in[4];
    const float* alpha1 = (const float*)d_in[5];
    const float* weight1= (const float*)d_in[6];
    const float* bias1  = (const float*)d_in[7];
    const float* W2     = (const float*)d_in[8];
    const float* b2     = (const float*)d_in[9];
    const float* alpha2 = (const float*)d_in[10];
    const float* weight2= (const float*)d_in[11];
    const float* bias2  = (const float*)d_in[12];
    float* out = (float*)d_out;

    int N = in_sizes[2];
    int E = in_sizes[1] / 2;
    const int* src = ei;
    const int* dst = ei + E;

    float *pA, *pB;
    cudaGetSymbolAddress((void**)&pA, g_bufA);
    cudaGetSymbolAddress((void**)&pB, g_bufB);

    const int T = 256;
    int nbN    = (N + T - 1) / T;
    int nbE    = (E + T - 1) / T;
    int nb16   = (N * 16 + T - 1) / T;
    int nbGF   = (NGRAPH * FDIM + T - 1) / T;
    int nbRow  = (N + 63) / 64;
    int nbWarp = (N * 32 + T - 1) / T;

    // ---- fork: preprocess chain on side stream, GEMM1 concurrently ----
    cudaEventRecord(g_aux.evFork, 0);
    cudaStreamWaitEvent(g_aux.s2, g_aux.evFork, 0);

    k_init <<<nbN, T, 0, g_aux.s2>>>(out, N);
    k_deg  <<<nbE, T, 0, g_aux.s2>>>(dst, E);
    k_alloc<<<nbN, T, 0, g_aux.s2>>>(batch, N);
    k_fill <<<nbE, T, 0, g_aux.s2>>>(src, dst, E);
    cudaEventRecord(g_aux.evJoin, g_aux.s2);

    // GEMM1 is independent of preprocessing (no dinv applied here)
    k_gemm<128, false><<<nbRow, T>>>(x, W1, pA, batch, N);

    cudaStreamWaitEvent(0, g_aux.evJoin, 0);   // join before gather

    // ---- layer 1 ----
    k_gather<<<nbWarp, T>>>(pA, pB, b1, batch, N);
    k_stats <<<nbGF, T>>>(alpha1, weight1, bias1);

    // ---- layer 2 (norm+relu fused into gemm load) ----
    k_gemm<64, true><<<nbRow, T>>>(pB, W2, pA, batch, N);
    k_gather<<<nbWarp, T>>>(pA, pB, b2, batch, N);
    k_stats <<<nbGF, T>>>(alpha2, weight2, bias2);

    // ---- pool ----
    k_apply_pool<<<nb16, T>>>(pB, out, batch, N);
}